// round 10
// baseline (speedup 1.0000x reference)
#include <cuda_runtime.h>
#include <math.h>

// ---------------- problem constants ----------------
#define T_STEPS 512
#define BATCH   256
#define FIN     64
#define HID     256
#define G3      768
#define ROWS_TOT (T_STEPS*BATCH)   // 131072

// recurrent kernel partitioning
#define R_GRID    128        // 8 batch tiles x 16 hidden tiles
#define R_THREADS 512        // 16 warps -> 4 per SMSP
#define RB        32         // batch rows per CTA
#define WSTRIDE   264        // weight smem stride: 3*264 % 32banks = 24 -> cg offsets {0,24,16,8}
#define INSTRIDE  260        // input stride: 2*260 % 32 = 8 -> rowpair offsets {0,8,16,24}
#define GSTRIDE   49         // gate result tile stride

// dynamic smem floats: 3 weight slices + 2 input tiles + 2 gate tiles
#define R_SMEM_FLOATS (3*48*WSTRIDE + 2*RB*INSTRIDE + 2*RB*GSTRIDE)
#define R_SMEM_BYTES  (R_SMEM_FLOATS*4)   // 231,168 B <= 232,448 opt-in max

// ---------------- device scratch (static: no allocs allowed) ----------------
__device__ float g_feats [(size_t)ROWS_TOT*HID];   // reused as value-net hidden
__device__ float g_gi0   [(size_t)ROWS_TOT*G3];    // layer0 gi incl b_ih0
__device__ float g_gruout[(size_t)ROWS_TOT*HID];
__device__ float g_hbuf  [2][2][BATCH][HID];       // [parity][layer][B][H] ping-pong
__device__ unsigned g_bar;

// ---------------- helpers ----------------
__device__ __forceinline__ float2 ffma2(float2 a, float2 b, float2 c) {
    unsigned long long au = *reinterpret_cast<unsigned long long*>(&a);
    unsigned long long bu = *reinterpret_cast<unsigned long long*>(&b);
    unsigned long long cu = *reinterpret_cast<unsigned long long*>(&c);
    unsigned long long du;
    asm("fma.rn.f32x2 %0, %1, %2, %3;" : "=l"(du) : "l"(au), "l"(bu), "l"(cu));
    return *reinterpret_cast<float2*>(&du);
}

__device__ __forceinline__ float sigmoidf_(float x) { return 1.0f / (1.0f + __expf(-x)); }

// local weight-row (0..47) -> global gate row for hidden base hb
__device__ __forceinline__ int grow_map(int hb, int c) {
    return (c < 16) ? (hb + c) : (c < 32) ? (256 + hb + (c - 16)) : (512 + hb + (c - 32));
}

__global__ void init_bar_kernel() { g_bar = 0u; }

// ---------------- generic tiled fp32 GEMM: C = act(A[M,K] @ W[N,K]^T + bias) ----------------
template <bool LRELU>
__global__ void __launch_bounds__(128) gemm_lin_kernel(
    const float* __restrict__ A, const float* __restrict__ W,
    const float* __restrict__ bias, float* __restrict__ C,
    int M, int N, int K)
{
    __shared__ __align__(16) float As[16][68];
    __shared__ __align__(16) float Bs[16][68];

    const int tid  = threadIdx.x;
    const int row0 = blockIdx.y * 64;
    const int col0 = blockIdx.x * 64;
    const int c0 = (tid & 15) * 4;
    const int r0 = (tid >> 4) * 8;

    float2 acc[4][4];
#pragma unroll
    for (int i = 0; i < 4; i++)
#pragma unroll
        for (int j = 0; j < 4; j++) acc[i][j] = make_float2(0.f, 0.f);

    for (int kt = 0; kt < K; kt += 16) {
#pragma unroll
        for (int i = 0; i < 2; i++) {
            int e  = tid + i * 128;
            int r  = e >> 2;
            int k4 = (e & 3) * 4;
            float4 va = *(const float4*)&A[(size_t)(row0 + r) * K + kt + k4];
            As[k4 + 0][r] = va.x; As[k4 + 1][r] = va.y; As[k4 + 2][r] = va.z; As[k4 + 3][r] = va.w;
            float4 vb = *(const float4*)&W[(size_t)(col0 + r) * K + kt + k4];
            Bs[k4 + 0][r] = vb.x; Bs[k4 + 1][r] = vb.y; Bs[k4 + 2][r] = vb.z; Bs[k4 + 3][r] = vb.w;
        }
        __syncthreads();
#pragma unroll
        for (int k = 0; k < 16; k++) {
            float4 a03 = *(const float4*)&As[k][r0];
            float4 a47 = *(const float4*)&As[k][r0 + 4];
            float4 b   = *(const float4*)&Bs[k][c0];
            float2 ap[4] = { make_float2(a03.x, a03.y), make_float2(a03.z, a03.w),
                             make_float2(a47.x, a47.y), make_float2(a47.z, a47.w) };
            float2 bd[4] = { make_float2(b.x, b.x), make_float2(b.y, b.y),
                             make_float2(b.z, b.z), make_float2(b.w, b.w) };
#pragma unroll
            for (int i = 0; i < 4; i++)
#pragma unroll
                for (int j = 0; j < 4; j++) acc[i][j] = ffma2(ap[i], bd[j], acc[i][j]);
        }
        __syncthreads();
    }

#pragma unroll
    for (int j = 0; j < 4; j++) {
        float bv = bias[col0 + c0 + j];
#pragma unroll
        for (int i = 0; i < 4; i++) {
            float v0 = acc[i][j].x + bv;
            float v1 = acc[i][j].y + bv;
            if (LRELU) { v0 = (v0 > 0.f) ? v0 : 0.01f * v0; v1 = (v1 > 0.f) ? v1 : 0.01f * v1; }
            C[(size_t)(row0 + r0 + 2 * i    ) * N + col0 + c0 + j] = v0;
            C[(size_t)(row0 + r0 + 2 * i + 1) * N + col0 + c0 + j] = v1;
        }
    }
}

// ---------------- recurrent tile GEMM (512 thr): out[32][48] = in[32][256] @ w[48][256]^T ----
// 16 warps; warp tile 8 rows x 12 cols; thread = 2 rows x 3 cols over half of K.
// lanes 0-15 K[0:128), lanes 16-31 K[128:256) with +4-float rotation so kh=0/kh=1
// address sets interleave across all 8 16B bank-chunks -> 1 crossbar phase per LDS.128.
// Cross-kh reduction via shfl_xor(16); lanes kh==0 write results.
__device__ __forceinline__ void gemm_tile(const float* __restrict__ in_s,
                                          const float* __restrict__ w_s,
                                          float* __restrict__ out_s,
                                          const float* __restrict__ bias_g,
                                          int hb, int tid)
{
    const int lane = tid & 31;
    const int warp = tid >> 5;          // 0..15
    const int wr   = warp >> 2;         // row tile 0..3
    const int wc   = warp & 3;          // col tile 0..3
    const int slot = lane & 15;
    const int kh   = lane >> 4;         // 0 / 1
    const int r0   = wr * 8 + (slot >> 2) * 2;   // rows r0, r0+1
    const int cg   = wc * 4 + (slot & 3);        // colgroup 0..15
    const int c0   = cg * 3;
    const int rot  = kh * 4;

    const float* i0 = in_s + (size_t)r0 * INSTRIDE + kh * 128;
    const float* i1 = i0 + INSTRIDE;
    const float* w0 = w_s + (size_t)(c0 + 0) * WSTRIDE + kh * 128;
    const float* w1 = w_s + (size_t)(c0 + 1) * WSTRIDE + kh * 128;
    const float* w2 = w_s + (size_t)(c0 + 2) * WSTRIDE + kh * 128;

    float2 a00 = make_float2(0.f, 0.f), a01 = a00, a02 = a00;
    float2 a10 = a00, a11 = a00, a12 = a00;

#pragma unroll 8
    for (int k4 = 0; k4 < 128; k4 += 4) {
        int kk = (k4 + rot) & 127;      // K-order rotation (dot product is order-free)
        float4 x0 = *(const float4*)(i0 + kk);
        float4 x1 = *(const float4*)(i1 + kk);
        float4 b0 = *(const float4*)(w0 + kk);
        float4 b1 = *(const float4*)(w1 + kk);
        float4 b2 = *(const float4*)(w2 + kk);
        float2 x0l = make_float2(x0.x, x0.y), x0h = make_float2(x0.z, x0.w);
        float2 x1l = make_float2(x1.x, x1.y), x1h = make_float2(x1.z, x1.w);
        float2 b0l = make_float2(b0.x, b0.y), b0h = make_float2(b0.z, b0.w);
        float2 b1l = make_float2(b1.x, b1.y), b1h = make_float2(b1.z, b1.w);
        float2 b2l = make_float2(b2.x, b2.y), b2h = make_float2(b2.z, b2.w);
        a00 = ffma2(x0l, b0l, a00); a00 = ffma2(x0h, b0h, a00);
        a01 = ffma2(x0l, b1l, a01); a01 = ffma2(x0h, b1h, a01);
        a02 = ffma2(x0l, b2l, a02); a02 = ffma2(x0h, b2h, a02);
        a10 = ffma2(x1l, b0l, a10); a10 = ffma2(x1h, b0h, a10);
        a11 = ffma2(x1l, b1l, a11); a11 = ffma2(x1h, b1h, a11);
        a12 = ffma2(x1l, b2l, a12); a12 = ffma2(x1h, b2h, a12);
    }

    float s00 = a00.x + a00.y, s01 = a01.x + a01.y, s02 = a02.x + a02.y;
    float s10 = a10.x + a10.y, s11 = a11.x + a11.y, s12 = a12.x + a12.y;
    s00 += __shfl_xor_sync(0xffffffffu, s00, 16);
    s01 += __shfl_xor_sync(0xffffffffu, s01, 16);
    s02 += __shfl_xor_sync(0xffffffffu, s02, 16);
    s10 += __shfl_xor_sync(0xffffffffu, s10, 16);
    s11 += __shfl_xor_sync(0xffffffffu, s11, 16);
    s12 += __shfl_xor_sync(0xffffffffu, s12, 16);

    if (kh == 0) {
        float bb0 = __ldg(&bias_g[grow_map(hb, c0 + 0)]);
        float bb1 = __ldg(&bias_g[grow_map(hb, c0 + 1)]);
        float bb2 = __ldg(&bias_g[grow_map(hb, c0 + 2)]);
        out_s[(r0    ) * GSTRIDE + c0 + 0] = s00 + bb0;
        out_s[(r0    ) * GSTRIDE + c0 + 1] = s01 + bb1;
        out_s[(r0    ) * GSTRIDE + c0 + 2] = s02 + bb2;
        out_s[(r0 + 1) * GSTRIDE + c0 + 0] = s10 + bb0;
        out_s[(r0 + 1) * GSTRIDE + c0 + 1] = s11 + bb1;
        out_s[(r0 + 1) * GSTRIDE + c0 + 2] = s12 + bb2;
    }
}

// ---------------- persistent recurrent kernel ----------------
// blk = bt*16 + ct ; bt = batch tile (32 rows), ct = hidden tile (16 units -> 48 gate rows)
__global__ void __launch_bounds__(R_THREADS, 1) recurrent_kernel(
    const int*   __restrict__ dones,
    const float* __restrict__ w_ih,   // [2][768][256]
    const float* __restrict__ w_hh,   // [2][768][256]
    const float* __restrict__ b_ih,   // [2][768]
    const float* __restrict__ b_hh)   // [2][768]
{
    extern __shared__ __align__(16) float smem[];
    float* w0s = smem;                       // w_hh0 slice [48][WSTRIDE]
    float* w1s = w0s + 48 * WSTRIDE;         // w_ih1 slice
    float* w2s = w1s + 48 * WSTRIDE;         // w_hh1 slice
    float* inA = w2s + 48 * WSTRIDE;         // [32][INSTRIDE]
    float* inB = inA + RB * INSTRIDE;        // [32][INSTRIDE]
    float* outA = inB + RB * INSTRIDE;       // [32][GSTRIDE]
    float* outB = outA + RB * GSTRIDE;       // [32][GSTRIDE]
    __shared__ float smask[RB];

    const int tid = threadIdx.x;
    const int bt  = blockIdx.x >> 4;
    const int ct  = blockIdx.x & 15;
    const int b0  = bt * RB;
    const int hb  = ct * 16;

    const float* w_hh0 = w_hh;
    const float* w_ih1 = w_ih + 768 * 256;
    const float* w_hh1 = w_hh + 768 * 256;
    const float* b_hh0 = b_hh;
    const float* b_ih1 = b_ih + 768;
    const float* b_hh1 = b_hh + 768;

    // ---- load persistent weight slices (resident in smem for all 512 steps) ----
    for (int idx = tid; idx < 48 * (HID / 4); idx += R_THREADS) {
        int c = idx >> 6, k4 = idx & 63;
        int gr = grow_map(hb, c);
        *(float4*)&w0s[c * WSTRIDE + k4 * 4] = *(const float4*)&w_hh0[gr * HID + k4 * 4];
        *(float4*)&w1s[c * WSTRIDE + k4 * 4] = *(const float4*)&w_ih1[gr * HID + k4 * 4];
        *(float4*)&w2s[c * WSTRIDE + k4 * 4] = *(const float4*)&w_hh1[gr * HID + k4 * 4];
    }
    __syncthreads();

    // gate-unit mapping: 512 threads -> exactly one (row, j) unit each
    const int grow0 = tid >> 4, gj0 = tid & 15;

    for (int t = 0; t < T_STEPS; t++) {
        const int rp = t & 1, wp = rp ^ 1;

        // ---- prefetch gi0 for this step's gate (DRAM, no reuse -> start early) ----
        size_t gb0 = ((size_t)t * BATCH + b0 + grow0) * G3 + hb + gj0;
        float p_r0 = __ldcs(&g_gi0[gb0]);
        float p_z0 = __ldcs(&g_gi0[gb0 + 256]);
        float p_n0 = __ldcs(&g_gi0[gb0 + 512]);

        // ---- done masks for this step ----
        if (tid < RB) smask[tid] = 1.0f - (float)dones[t * BATCH + b0 + tid];
        __syncthreads();

        // ===== phase 1: layer 0 =====
        // inA = mask * h0_prev
        for (int idx = tid; idx < RB * HID / 4; idx += R_THREADS) {
            int row = idx >> 6, k4 = idx & 63;
            float4 v = __ldcg((const float4*)&g_hbuf[rp][0][b0 + row][k4 * 4]);
            float m = smask[row];
            v.x *= m; v.y *= m; v.z *= m; v.w *= m;
            *(float4*)&inA[row * INSTRIDE + k4 * 4] = v;
        }
        __syncthreads();

        gemm_tile(inA, w0s, outA, b_hh0, hb, tid);   // gh0 tile
        __syncthreads();

        // gates layer 0: one unit per thread, prefetched gi
        {
            float gh_r = outA[grow0 * GSTRIDE + gj0];
            float gh_z = outA[grow0 * GSTRIDE + 16 + gj0];
            float gh_n = outA[grow0 * GSTRIDE + 32 + gj0];
            float r = sigmoidf_(p_r0 + gh_r);
            float z = sigmoidf_(p_z0 + gh_z);
            float n = tanhf(p_n0 + r * gh_n);
            float hm = inA[grow0 * INSTRIDE + hb + gj0];    // already masked
            __stcg(&g_hbuf[wp][0][b0 + grow0][hb + gj0], (1.0f - z) * n + z * hm);
        }

        // ---- single grid barrier per step (phase1 -> phase2) ----
        // All cross-step hazards transitively ordered by this barrier (R5 matrix).
        __syncthreads();
        if (tid == 0) {
            __threadfence();
            atomicAdd(&g_bar, 1u);
            unsigned target = (unsigned)(t + 1) * R_GRID;
            while (*((volatile unsigned*)&g_bar) < target) __nanosleep(32);
            __threadfence();
        }
        __syncthreads();

        // ===== phase 2: layer 1 =====
        // inA = h0_new (no mask), inB = mask * h1_prev
        for (int idx = tid; idx < RB * HID / 4; idx += R_THREADS) {
            int row = idx >> 6, k4 = idx & 63;
            float4 v = __ldcg((const float4*)&g_hbuf[wp][0][b0 + row][k4 * 4]);
            *(float4*)&inA[row * INSTRIDE + k4 * 4] = v;
            float4 u = __ldcg((const float4*)&g_hbuf[rp][1][b0 + row][k4 * 4]);
            float m = smask[row];
            u.x *= m; u.y *= m; u.z *= m; u.w *= m;
            *(float4*)&inB[row * INSTRIDE + k4 * 4] = u;
        }
        __syncthreads();

        gemm_tile(inA, w1s, outA, b_ih1, hb, tid);   // gi1 tile
        gemm_tile(inB, w2s, outB, b_hh1, hb, tid);   // gh1 tile
        __syncthreads();

        // gates layer 1: one unit per thread
        {
            float gi_r = outA[grow0 * GSTRIDE + gj0];
            float gi_z = outA[grow0 * GSTRIDE + 16 + gj0];
            float gi_n = outA[grow0 * GSTRIDE + 32 + gj0];
            float gh_r = outB[grow0 * GSTRIDE + gj0];
            float gh_z = outB[grow0 * GSTRIDE + 16 + gj0];
            float gh_n = outB[grow0 * GSTRIDE + 32 + gj0];
            float r = sigmoidf_(gi_r + gh_r);
            float z = sigmoidf_(gi_z + gh_z);
            float n = tanhf(gi_n + r * gh_n);
            float hm = inB[grow0 * INSTRIDE + hb + gj0];     // masked h1_prev
            float hnew = (1.0f - z) * n + z * hm;
            __stcg(&g_hbuf[wp][1][b0 + grow0][hb + gj0], hnew);
            g_gruout[((size_t)t * BATCH + b0 + grow0) * HID + hb + gj0] = hnew;
        }
        __syncthreads();
    }
}

// ---------------- value head final reduction: v = hidden @ w_v2^T + b_v2 ----------------
__global__ void __launch_bounds__(256) vhead_kernel(
    const float* __restrict__ hidden, const float* __restrict__ w_v2,
    const float* __restrict__ b_v2, float* __restrict__ out)
{
    int row  = blockIdx.x * 8 + (threadIdx.x >> 5);
    int lane = threadIdx.x & 31;
    const float4* hp = (const float4*)(hidden + (size_t)row * HID);
    const float4* wp = (const float4*)w_v2;
    float s = 0.f;
#pragma unroll
    for (int i = 0; i < 2; i++) {
        float4 h4 = hp[lane * 2 + i];
        float4 w4 = __ldg(&wp[lane * 2 + i]);
        s += h4.x * w4.x + h4.y * w4.y + h4.z * w4.z + h4.w * w4.w;
    }
#pragma unroll
    for (int off = 16; off; off >>= 1) s += __shfl_xor_sync(0xffffffffu, s, off);
    if (lane == 0) out[row] = s + b_v2[0];
}

// ---------------- launch ----------------
extern "C" void kernel_launch(void* const* d_in, const int* in_sizes, int n_in,
                              void* d_out, int out_size) {
    const float* x        = (const float*)d_in[0];
    const int*   dones    = (const int*)  d_in[1];
    const float* h0       = (const float*)d_in[2];
    const float* w_shared = (const float*)d_in[3];
    const float* b_shared = (const float*)d_in[4];
    const float* w_ih     = (const float*)d_in[5];
    const float* w_hh     = (const float*)d_in[6];
    const float* b_ih     = (const float*)d_in[7];
    const float* b_hh     = (const float*)d_in[8];
    const float* w_v1     = (const float*)d_in[9];
    const float* b_v1     = (const float*)d_in[10];
    const float* w_v2     = (const float*)d_in[11];
    const float* b_v2     = (const float*)d_in[12];
    float* out = (float*)d_out;

    // idempotent, capture-safe (not a stream op)
    cudaFuncSetAttribute(recurrent_kernel,
                         cudaFuncAttributeMaxDynamicSharedMemorySize, R_SMEM_BYTES);

    float* featsP;  cudaGetSymbolAddress((void**)&featsP,  g_feats);
    float* gi0P;    cudaGetSymbolAddress((void**)&gi0P,    g_gi0);
    float* gruoutP; cudaGetSymbolAddress((void**)&gruoutP, g_gruout);
    float* hiddenP = featsP;   // overlay: feats is dead after gi0 GEMM

    // reset barrier + seed h ping-pong (parity 0) with h0
    init_bar_kernel<<<1, 1>>>();
    cudaMemcpyToSymbolAsync(g_hbuf, h0, (size_t)2 * BATCH * HID * sizeof(float),
                            0, cudaMemcpyDeviceToDevice, 0);

    // feats = LReLU(x @ w_shared^T + b_shared)  [131072, 256]
    {
        dim3 g(HID / 64, ROWS_TOT / 64);
        gemm_lin_kernel<true><<<g, 128>>>(x, w_shared, b_shared, featsP,
                                          ROWS_TOT, HID, FIN);
    }
    // gi0 = feats @ w_ih0^T + b_ih0  [131072, 768]
    {
        dim3 g(G3 / 64, ROWS_TOT / 64);
        gemm_lin_kernel<false><<<g, 128>>>(featsP, w_ih, b_ih, gi0P,
                                           ROWS_TOT, G3, HID);
    }
    // sequential GRU rollout (persistent, grid-resident)
    recurrent_kernel<<<R_GRID, R_THREADS, R_SMEM_BYTES>>>(dones, w_ih, w_hh, b_ih, b_hh);

    // hidden = LReLU(gruout @ w_v1^T + b_v1)   (overwrites g_feats)
    {
        dim3 g(HID / 64, ROWS_TOT / 64);
        gemm_lin_kernel<true><<<g, 128>>>(gruoutP, w_v1, b_v1, hiddenP,
                                          ROWS_TOT, HID, HID);
    }
    // v = hidden @ w_v2^T + b_v2  -> out[0 : 131072)
    vhead_kernel<<<ROWS_TOT / 8, 256>>>(hiddenP, w_v2, b_v2, out);

    // h_final lives in parity 0 after 512 steps -> out[131072 : 262144)
    if (out_size >= 2 * ROWS_TOT) {
        cudaMemcpyFromSymbolAsync(out + ROWS_TOT, g_hbuf,
                                  (size_t)2 * BATCH * HID * sizeof(float),
                                  0, cudaMemcpyDeviceToDevice, 0);
    }
}

// round 11
// speedup vs baseline: 1.2730x; 1.2730x over previous
#include <cuda_runtime.h>
#include <math.h>

// ---------------- problem constants ----------------
#define T_STEPS 512
#define BATCH   256
#define FIN     64
#define HID     256
#define G3      768
#define ROWS_TOT (T_STEPS*BATCH)   // 131072

// recurrent kernel partitioning
#define R_GRID    128        // 8 batch tiles x 16 hidden tiles
#define R_THREADS 512        // 16 warps
#define RB        32         // batch rows per CTA
#define WSTRIDE   268        // weight stride: 268%16==12 -> 6*W%32==8 -> colgroups at {0,8,16,24}
#define INSTRIDE  256        // input stride (row uniform per instr -> stride-agnostic)
#define GSTRIDE   48         // gate result tile stride

// dynamic smem floats: 3 weight slices + 2 input tiles + 2 gate tiles + mask
#define R_SMEM_FLOATS (3*48*WSTRIDE + 2*RB*INSTRIDE + 2*RB*GSTRIDE + RB)
#define R_SMEM_BYTES  (R_SMEM_FLOATS*4)   // 232,320 B <= 232,448 opt-in max

// ---------------- device scratch (static: no allocs allowed) ----------------
__device__ float g_feats [(size_t)ROWS_TOT*HID];   // reused as value-net hidden
__device__ float g_gi0   [(size_t)ROWS_TOT*G3];    // layer0 gi incl b_ih0
__device__ float g_gruout[(size_t)ROWS_TOT*HID];
__device__ float g_hbuf  [2][2][BATCH][HID];       // [parity][layer][B][H] ping-pong
__device__ unsigned g_bar;

// ---------------- helpers ----------------
__device__ __forceinline__ float2 ffma2(float2 a, float2 b, float2 c) {
    unsigned long long au = *reinterpret_cast<unsigned long long*>(&a);
    unsigned long long bu = *reinterpret_cast<unsigned long long*>(&b);
    unsigned long long cu = *reinterpret_cast<unsigned long long*>(&c);
    unsigned long long du;
    asm("fma.rn.f32x2 %0, %1, %2, %3;" : "=l"(du) : "l"(au), "l"(bu), "l"(cu));
    return *reinterpret_cast<float2*>(&du);
}

__device__ __forceinline__ float sigmoidf_(float x) { return 1.0f / (1.0f + __expf(-x)); }

// local weight-row (0..47) -> global gate row for hidden base hb
__device__ __forceinline__ int grow_map(int hb, int c) {
    return (c < 16) ? (hb + c) : (c < 32) ? (256 + hb + (c - 16)) : (512 + hb + (c - 32));
}

__global__ void init_bar_kernel() { g_bar = 0u; }

// ---------------- generic tiled fp32 GEMM: C = act(A[M,K] @ W[N,K]^T + bias) ----------------
template <bool LRELU>
__global__ void __launch_bounds__(128) gemm_lin_kernel(
    const float* __restrict__ A, const float* __restrict__ W,
    const float* __restrict__ bias, float* __restrict__ C,
    int M, int N, int K)
{
    __shared__ __align__(16) float As[16][68];
    __shared__ __align__(16) float Bs[16][68];

    const int tid  = threadIdx.x;
    const int row0 = blockIdx.y * 64;
    const int col0 = blockIdx.x * 64;
    const int c0 = (tid & 15) * 4;
    const int r0 = (tid >> 4) * 8;

    float2 acc[4][4];
#pragma unroll
    for (int i = 0; i < 4; i++)
#pragma unroll
        for (int j = 0; j < 4; j++) acc[i][j] = make_float2(0.f, 0.f);

    for (int kt = 0; kt < K; kt += 16) {
#pragma unroll
        for (int i = 0; i < 2; i++) {
            int e  = tid + i * 128;
            int r  = e >> 2;
            int k4 = (e & 3) * 4;
            float4 va = *(const float4*)&A[(size_t)(row0 + r) * K + kt + k4];
            As[k4 + 0][r] = va.x; As[k4 + 1][r] = va.y; As[k4 + 2][r] = va.z; As[k4 + 3][r] = va.w;
            float4 vb = *(const float4*)&W[(size_t)(col0 + r) * K + kt + k4];
            Bs[k4 + 0][r] = vb.x; Bs[k4 + 1][r] = vb.y; Bs[k4 + 2][r] = vb.z; Bs[k4 + 3][r] = vb.w;
        }
        __syncthreads();
#pragma unroll
        for (int k = 0; k < 16; k++) {
            float4 a03 = *(const float4*)&As[k][r0];
            float4 a47 = *(const float4*)&As[k][r0 + 4];
            float4 b   = *(const float4*)&Bs[k][c0];
            float2 ap[4] = { make_float2(a03.x, a03.y), make_float2(a03.z, a03.w),
                             make_float2(a47.x, a47.y), make_float2(a47.z, a47.w) };
            float2 bd[4] = { make_float2(b.x, b.x), make_float2(b.y, b.y),
                             make_float2(b.z, b.z), make_float2(b.w, b.w) };
#pragma unroll
            for (int i = 0; i < 4; i++)
#pragma unroll
                for (int j = 0; j < 4; j++) acc[i][j] = ffma2(ap[i], bd[j], acc[i][j]);
        }
        __syncthreads();
    }

#pragma unroll
    for (int j = 0; j < 4; j++) {
        float bv = bias[col0 + c0 + j];
#pragma unroll
        for (int i = 0; i < 4; i++) {
            float v0 = acc[i][j].x + bv;
            float v1 = acc[i][j].y + bv;
            if (LRELU) { v0 = (v0 > 0.f) ? v0 : 0.01f * v0; v1 = (v1 > 0.f) ? v1 : 0.01f * v1; }
            C[(size_t)(row0 + r0 + 2 * i    ) * N + col0 + c0 + j] = v0;
            C[(size_t)(row0 + r0 + 2 * i + 1) * N + col0 + c0 + j] = v1;
        }
    }
}

// ---------------- recurrent tile GEMM (512 thr): out[32][48] = in[32][256] @ w[48][256]^T ----
// Thread tile 4 rows x 6 cols, split-K-8 (chunks of 32).
// lane = kc*4 + s : kc = K-chunk (0..7), s selects col-group within warp.
// warp w: rowgroup rg = w>>1 (rows rg*4..+3), colgroup cg = (w&1)*4 + s (cols cg*6..+5).
// Per 4-k: 10 LDS.128 feed 96 FMAs (0.42 loads/FMA vs 0.83 in the 2x3 scheme).
// kk rotation (+4*kc) spreads the 8 kc-chunks across all 32 banks; WSTRIDE=268 makes
// the 4 col-groups land at bank offsets {0,8,16,24} -> conflict-free wavefronts.
// Cross-kc reduction: 3x shfl_xor; kc==0 lanes add bias and write.
__device__ __forceinline__ void gemm_tile(const float* __restrict__ in_s,
                                          const float* __restrict__ w_s,
                                          float* __restrict__ out_s,
                                          const float* __restrict__ bias_g,
                                          int hb, int tid)
{
    const int lane = tid & 31;
    const int warp = tid >> 5;            // 0..15
    const int kc   = lane >> 2;           // 0..7
    const int s    = lane & 3;            // 0..3
    const int rg   = warp >> 1;           // 0..7 -> rows rg*4..rg*4+3
    const int cg   = (warp & 1) * 4 + s;  // 0..7 -> cols cg*6..cg*6+5
    const int rot  = kc * 4;

    const float* pin = in_s + (size_t)(rg * 4) * INSTRIDE + kc * 32;
    const float* pw  = w_s  + (size_t)(cg * 6) * WSTRIDE  + kc * 32;

    float2 acc[4][6];
#pragma unroll
    for (int i = 0; i < 4; i++)
#pragma unroll
        for (int j = 0; j < 6; j++) acc[i][j] = make_float2(0.f, 0.f);

#pragma unroll
    for (int it = 0; it < 8; it++) {
        int kk = rot + it * 4; if (kk >= 32) kk -= 32;
        float4 x0 = *(const float4*)(pin + 0 * INSTRIDE + kk);
        float4 x1 = *(const float4*)(pin + 1 * INSTRIDE + kk);
        float4 x2 = *(const float4*)(pin + 2 * INSTRIDE + kk);
        float4 x3 = *(const float4*)(pin + 3 * INSTRIDE + kk);
        float2 xl[4] = { make_float2(x0.x, x0.y), make_float2(x1.x, x1.y),
                         make_float2(x2.x, x2.y), make_float2(x3.x, x3.y) };
        float2 xh[4] = { make_float2(x0.z, x0.w), make_float2(x1.z, x1.w),
                         make_float2(x2.z, x2.w), make_float2(x3.z, x3.w) };
#pragma unroll
        for (int j = 0; j < 6; j++) {
            float4 wv = *(const float4*)(pw + j * WSTRIDE + kk);
            float2 wl = make_float2(wv.x, wv.y);
            float2 wh = make_float2(wv.z, wv.w);
#pragma unroll
            for (int i = 0; i < 4; i++) {
                acc[i][j] = ffma2(xl[i], wl, acc[i][j]);
                acc[i][j] = ffma2(xh[i], wh, acc[i][j]);
            }
        }
    }

    // collapse float2 -> scalar, reduce across the 8 kc lanes (stride 4)
    float red[4][6];
#pragma unroll
    for (int i = 0; i < 4; i++)
#pragma unroll
        for (int j = 0; j < 6; j++) {
            float v = acc[i][j].x + acc[i][j].y;
            v += __shfl_xor_sync(0xffffffffu, v, 16);
            v += __shfl_xor_sync(0xffffffffu, v, 8);
            v += __shfl_xor_sync(0xffffffffu, v, 4);
            red[i][j] = v;
        }

    if (kc == 0) {
#pragma unroll
        for (int j = 0; j < 6; j++) {
            int col = cg * 6 + j;
            float bb = __ldg(&bias_g[grow_map(hb, col)]);
#pragma unroll
            for (int i = 0; i < 4; i++)
                out_s[(rg * 4 + i) * GSTRIDE + col] = red[i][j] + bb;
        }
    }
}

// ---------------- persistent recurrent kernel ----------------
// blk = bt*16 + ct ; bt = batch tile (32 rows), ct = hidden tile (16 units -> 48 gate rows)
__global__ void __launch_bounds__(R_THREADS, 1) recurrent_kernel(
    const int*   __restrict__ dones,
    const float* __restrict__ w_ih,   // [2][768][256]
    const float* __restrict__ w_hh,   // [2][768][256]
    const float* __restrict__ b_ih,   // [2][768]
    const float* __restrict__ b_hh)   // [2][768]
{
    extern __shared__ __align__(16) float smem[];
    float* w0s   = smem;                       // w_hh0 slice [48][WSTRIDE]
    float* w1s   = w0s + 48 * WSTRIDE;         // w_ih1 slice
    float* w2s   = w1s + 48 * WSTRIDE;         // w_hh1 slice
    float* inA   = w2s + 48 * WSTRIDE;         // [32][INSTRIDE]
    float* inB   = inA + RB * INSTRIDE;        // [32][INSTRIDE]
    float* outA  = inB + RB * INSTRIDE;        // [32][GSTRIDE]
    float* outB  = outA + RB * GSTRIDE;        // [32][GSTRIDE]
    float* smask = outB + RB * GSTRIDE;        // [32]

    const int tid = threadIdx.x;
    const int bt  = blockIdx.x >> 4;
    const int ct  = blockIdx.x & 15;
    const int b0  = bt * RB;
    const int hb  = ct * 16;

    const float* w_hh0 = w_hh;
    const float* w_ih1 = w_ih + 768 * 256;
    const float* w_hh1 = w_hh + 768 * 256;
    const float* b_hh0 = b_hh;
    const float* b_ih1 = b_ih + 768;
    const float* b_hh1 = b_hh + 768;

    // ---- load persistent weight slices (resident in smem for all 512 steps) ----
    for (int idx = tid; idx < 48 * (HID / 4); idx += R_THREADS) {
        int c = idx >> 6, k4 = idx & 63;
        int gr = grow_map(hb, c);
        *(float4*)&w0s[c * WSTRIDE + k4 * 4] = *(const float4*)&w_hh0[gr * HID + k4 * 4];
        *(float4*)&w1s[c * WSTRIDE + k4 * 4] = *(const float4*)&w_ih1[gr * HID + k4 * 4];
        *(float4*)&w2s[c * WSTRIDE + k4 * 4] = *(const float4*)&w_hh1[gr * HID + k4 * 4];
    }
    __syncthreads();

    // gate-unit mapping: 512 threads -> exactly one (row, j) unit each
    const int grow0 = tid >> 4, gj0 = tid & 15;

    for (int t = 0; t < T_STEPS; t++) {
        const int rp = t & 1, wp = rp ^ 1;

        // ---- prefetch gi0 for this step's gate (DRAM, no reuse -> start early) ----
        size_t gb0 = ((size_t)t * BATCH + b0 + grow0) * G3 + hb + gj0;
        float p_r0 = __ldcs(&g_gi0[gb0]);
        float p_z0 = __ldcs(&g_gi0[gb0 + 256]);
        float p_n0 = __ldcs(&g_gi0[gb0 + 512]);

        // ---- done masks for this step ----
        if (tid < RB) smask[tid] = 1.0f - (float)dones[t * BATCH + b0 + tid];
        __syncthreads();

        // ===== phase 1: layer 0 =====
        // inA = mask * h0_prev
        for (int idx = tid; idx < RB * HID / 4; idx += R_THREADS) {
            int row = idx >> 6, k4 = idx & 63;
            float4 v = __ldcg((const float4*)&g_hbuf[rp][0][b0 + row][k4 * 4]);
            float m = smask[row];
            v.x *= m; v.y *= m; v.z *= m; v.w *= m;
            *(float4*)&inA[row * INSTRIDE + k4 * 4] = v;
        }
        __syncthreads();

        gemm_tile(inA, w0s, outA, b_hh0, hb, tid);   // gh0 tile
        __syncthreads();

        // gates layer 0: one unit per thread, prefetched gi
        {
            float gh_r = outA[grow0 * GSTRIDE + gj0];
            float gh_z = outA[grow0 * GSTRIDE + 16 + gj0];
            float gh_n = outA[grow0 * GSTRIDE + 32 + gj0];
            float r = sigmoidf_(p_r0 + gh_r);
            float z = sigmoidf_(p_z0 + gh_z);
            float n = tanhf(p_n0 + r * gh_n);
            float hm = inA[grow0 * INSTRIDE + hb + gj0];    // already masked
            __stcg(&g_hbuf[wp][0][b0 + grow0][hb + gj0], (1.0f - z) * n + z * hm);
        }

        // ---- single grid barrier per step (phase1 -> phase2) ----
        // All cross-step hazards transitively ordered by this barrier (R5 matrix).
        __syncthreads();
        if (tid == 0) {
            __threadfence();
            atomicAdd(&g_bar, 1u);
            unsigned target = (unsigned)(t + 1) * R_GRID;
            while (*((volatile unsigned*)&g_bar) < target) __nanosleep(32);
            __threadfence();
        }
        __syncthreads();

        // ===== phase 2: layer 1 =====
        // inA = h0_new (no mask), inB = mask * h1_prev
        for (int idx = tid; idx < RB * HID / 4; idx += R_THREADS) {
            int row = idx >> 6, k4 = idx & 63;
            float4 v = __ldcg((const float4*)&g_hbuf[wp][0][b0 + row][k4 * 4]);
            *(float4*)&inA[row * INSTRIDE + k4 * 4] = v;
            float4 u = __ldcg((const float4*)&g_hbuf[rp][1][b0 + row][k4 * 4]);
            float m = smask[row];
            u.x *= m; u.y *= m; u.z *= m; u.w *= m;
            *(float4*)&inB[row * INSTRIDE + k4 * 4] = u;
        }
        __syncthreads();

        gemm_tile(inA, w1s, outA, b_ih1, hb, tid);   // gi1 tile
        gemm_tile(inB, w2s, outB, b_hh1, hb, tid);   // gh1 tile
        __syncthreads();

        // gates layer 1: one unit per thread
        {
            float gi_r = outA[grow0 * GSTRIDE + gj0];
            float gi_z = outA[grow0 * GSTRIDE + 16 + gj0];
            float gi_n = outA[grow0 * GSTRIDE + 32 + gj0];
            float gh_r = outB[grow0 * GSTRIDE + gj0];
            float gh_z = outB[grow0 * GSTRIDE + 16 + gj0];
            float gh_n = outB[grow0 * GSTRIDE + 32 + gj0];
            float r = sigmoidf_(gi_r + gh_r);
            float z = sigmoidf_(gi_z + gh_z);
            float n = tanhf(gi_n + r * gh_n);
            float hm = inB[grow0 * INSTRIDE + hb + gj0];     // masked h1_prev
            float hnew = (1.0f - z) * n + z * hm;
            __stcg(&g_hbuf[wp][1][b0 + grow0][hb + gj0], hnew);
            g_gruout[((size_t)t * BATCH + b0 + grow0) * HID + hb + gj0] = hnew;
        }
        __syncthreads();
    }
}

// ---------------- value head final reduction: v = hidden @ w_v2^T + b_v2 ----------------
__global__ void __launch_bounds__(256) vhead_kernel(
    const float* __restrict__ hidden, const float* __restrict__ w_v2,
    const float* __restrict__ b_v2, float* __restrict__ out)
{
    int row  = blockIdx.x * 8 + (threadIdx.x >> 5);
    int lane = threadIdx.x & 31;
    const float4* hp = (const float4*)(hidden + (size_t)row * HID);
    const float4* wp = (const float4*)w_v2;
    float s = 0.f;
#pragma unroll
    for (int i = 0; i < 2; i++) {
        float4 h4 = hp[lane * 2 + i];
        float4 w4 = __ldg(&wp[lane * 2 + i]);
        s += h4.x * w4.x + h4.y * w4.y + h4.z * w4.z + h4.w * w4.w;
    }
#pragma unroll
    for (int off = 16; off; off >>= 1) s += __shfl_xor_sync(0xffffffffu, s, off);
    if (lane == 0) out[row] = s + b_v2[0];
}

// ---------------- launch ----------------
extern "C" void kernel_launch(void* const* d_in, const int* in_sizes, int n_in,
                              void* d_out, int out_size) {
    const float* x        = (const float*)d_in[0];
    const int*   dones    = (const int*)  d_in[1];
    const float* h0       = (const float*)d_in[2];
    const float* w_shared = (const float*)d_in[3];
    const float* b_shared = (const float*)d_in[4];
    const float* w_ih     = (const float*)d_in[5];
    const float* w_hh     = (const float*)d_in[6];
    const float* b_ih     = (const float*)d_in[7];
    const float* b_hh     = (const float*)d_in[8];
    const float* w_v1     = (const float*)d_in[9];
    const float* b_v1     = (const float*)d_in[10];
    const float* w_v2     = (const float*)d_in[11];
    const float* b_v2     = (const float*)d_in[12];
    float* out = (float*)d_out;

    // idempotent, capture-safe (not a stream op)
    cudaFuncSetAttribute(recurrent_kernel,
                         cudaFuncAttributeMaxDynamicSharedMemorySize, R_SMEM_BYTES);

    float* featsP;  cudaGetSymbolAddress((void**)&featsP,  g_feats);
    float* gi0P;    cudaGetSymbolAddress((void**)&gi0P,    g_gi0);
    float* gruoutP; cudaGetSymbolAddress((void**)&gruoutP, g_gruout);
    float* hiddenP = featsP;   // overlay: feats is dead after gi0 GEMM

    // reset barrier + seed h ping-pong (parity 0) with h0
    init_bar_kernel<<<1, 1>>>();
    cudaMemcpyToSymbolAsync(g_hbuf, h0, (size_t)2 * BATCH * HID * sizeof(float),
                            0, cudaMemcpyDeviceToDevice, 0);

    // feats = LReLU(x @ w_shared^T + b_shared)  [131072, 256]
    {
        dim3 g(HID / 64, ROWS_TOT / 64);
        gemm_lin_kernel<true><<<g, 128>>>(x, w_shared, b_shared, featsP,
                                          ROWS_TOT, HID, FIN);
    }
    // gi0 = feats @ w_ih0^T + b_ih0  [131072, 768]
    {
        dim3 g(G3 / 64, ROWS_TOT / 64);
        gemm_lin_kernel<false><<<g, 128>>>(featsP, w_ih, b_ih, gi0P,
                                           ROWS_TOT, G3, HID);
    }
    // sequential GRU rollout (persistent, grid-resident)
    recurrent_kernel<<<R_GRID, R_THREADS, R_SMEM_BYTES>>>(dones, w_ih, w_hh, b_ih, b_hh);

    // hidden = LReLU(gruout @ w_v1^T + b_v1)   (overwrites g_feats)
    {
        dim3 g(HID / 64, ROWS_TOT / 64);
        gemm_lin_kernel<true><<<g, 128>>>(gruoutP, w_v1, b_v1, hiddenP,
                                          ROWS_TOT, HID, HID);
    }
    // v = hidden @ w_v2^T + b_v2  -> out[0 : 131072)
    vhead_kernel<<<ROWS_TOT / 8, 256>>>(hiddenP, w_v2, b_v2, out);

    // h_final lives in parity 0 after 512 steps -> out[131072 : 262144)
    if (out_size >= 2 * ROWS_TOT) {
        cudaMemcpyFromSymbolAsync(out + ROWS_TOT, g_hbuf,
                                  (size_t)2 * BATCH * HID * sizeof(float),
                                  0, cudaMemcpyDeviceToDevice, 0);
    }
}